// round 1
// baseline (speedup 1.0000x reference)
#include <cuda_runtime.h>
#include <stdint.h>

#define B 64
#define T 512
#define D 384
#define MAX_LEN 4096
#define D4 (D / 4)   // 96 float4 per row

// scratch: expanded frame index per output position, -1 = masked/zero
__device__ int g_idx[B * MAX_LEN];

// ---------------------------------------------------------------------------
// Kernel A: per-batch cumsum of durations, scatter frame index, tail fill,
// and mel_len write. One block per batch, 512 threads (one per frame).
// ---------------------------------------------------------------------------
__global__ void lr_scan_scatter(const int* __restrict__ duration,
                                float* __restrict__ out_tail /* mel_len as f32 */)
{
    __shared__ int s_csum[T];
    const int b = blockIdx.x;
    const int t = threadIdx.x;

    int v = duration[b * T + t];
    s_csum[t] = v;
    __syncthreads();

    // Hillis-Steele inclusive scan over 512 elements
    #pragma unroll
    for (int off = 1; off < T; off <<= 1) {
        int add = (t >= off) ? s_csum[t - off] : 0;
        __syncthreads();
        s_csum[t] += add;
        __syncthreads();
    }

    const int end   = s_csum[t];
    const int start = end - v;                 // == csum[t-1]
    const int mel   = s_csum[T - 1];

    int* idx_b = g_idx + b * MAX_LEN;
    // scatter: positions [start, end) map to frame t  (<= 7 iterations)
    for (int p = start; p < end; ++p) idx_b[p] = t;

    // tail: positions >= mel_len are zeros
    for (int p = mel + t; p < MAX_LEN; p += T) idx_b[p] = -1;

    if (t == 0) out_tail[b] = (float)mel;
}

// ---------------------------------------------------------------------------
// Kernel B: flat float4 gather. One thread per float4 of the output.
// total float4 = B * MAX_LEN * D4 = 25,165,824
// ---------------------------------------------------------------------------
__global__ void lr_gather(const float4* __restrict__ x,   // [B, T, D4]
                          float4* __restrict__ out)        // [B, MAX_LEN, D4]
{
    const long long gid = (long long)blockIdx.x * blockDim.x + threadIdx.x;
    const long long total = (long long)B * MAX_LEN * D4;
    if (gid >= total) return;

    const int d4 = (int)(gid % D4);
    const int bp = (int)(gid / D4);           // b * MAX_LEN + p
    const int b  = bp >> 12;                  // / MAX_LEN

    const int idx = __ldg(&g_idx[bp]);

    float4 r;
    if (idx < 0) {
        r = make_float4(0.f, 0.f, 0.f, 0.f);
    } else {
        r = __ldg(&x[((long long)b * T + idx) * D4 + d4]);
    }
    out[gid] = r;
}

extern "C" void kernel_launch(void* const* d_in, const int* in_sizes, int n_in,
                              void* d_out, int out_size)
{
    const float* x        = (const float*)d_in[0];
    const int*   duration = (const int*)d_in[1];
    // d_in[2] = max_len scalar (compile-time constant here)

    float* out = (float*)d_out;
    float* out_tail = out + (size_t)B * MAX_LEN * D;   // mel_len region (64 floats)

    lr_scan_scatter<<<B, T>>>(duration, out_tail);

    const long long total4 = (long long)B * MAX_LEN * D4;
    const int threads = 256;
    const int blocks  = (int)((total4 + threads - 1) / threads);
    lr_gather<<<blocks, threads>>>((const float4*)x, (float4*)out);
}

// round 2
// speedup vs baseline: 1.4213x; 1.4213x over previous
#include <cuda_runtime.h>
#include <stdint.h>

#define B 64
#define T 512
#define D 384
#define MAX_LEN 4096
#define D4 (D / 4)          // 96 float4 per row
#define ROWS_PER_WARP 4

// scratch: source frame index per output position, -1 = masked (write zeros)
__device__ int g_idx[B * MAX_LEN];

// ---------------------------------------------------------------------------
// Kernel A: per-batch cumsum of durations, scatter frame index, tail fill,
// and mel_len write. One block per batch, 512 threads (one per frame).
// ---------------------------------------------------------------------------
__global__ void lr_scan_scatter(const int* __restrict__ duration,
                                float* __restrict__ out_tail /* mel_len as f32 */)
{
    __shared__ int s_csum[T];
    const int b = blockIdx.x;
    const int t = threadIdx.x;

    int v = duration[b * T + t];
    s_csum[t] = v;
    __syncthreads();

    #pragma unroll
    for (int off = 1; off < T; off <<= 1) {
        int add = (t >= off) ? s_csum[t - off] : 0;
        __syncthreads();
        s_csum[t] += add;
        __syncthreads();
    }

    const int end   = s_csum[t];
    const int start = end - v;                 // == csum[t-1]
    const int mel   = s_csum[T - 1];

    int* idx_b = g_idx + b * MAX_LEN;
    for (int p = start; p < end; ++p) idx_b[p] = t;          // <= 7 iters
    for (int p = mel + t; p < MAX_LEN; p += T) idx_b[p] = -1; // masked tail

    if (t == 0) out_tail[b] = (float)mel;
}

// ---------------------------------------------------------------------------
// Kernel B: warp-per-row gather, 4 rows per warp.
// Row = (b, p). Lanes cover d4 = {lane, lane+32, lane+64}.
// All 12 loads issued before any store -> MLP ~12 per thread.
// total rows = B*MAX_LEN = 262144; warps = 65536; blocks(256) = 8192 (exact).
// ---------------------------------------------------------------------------
__global__ void lr_gather(const float4* __restrict__ x,   // [B, T, D4]
                          float4* __restrict__ out)        // [B, MAX_LEN, D4]
{
    const int warp = (blockIdx.x * blockDim.x + threadIdx.x) >> 5;
    const int lane = threadIdx.x & 31;
    const int row0 = warp * ROWS_PER_WARP;    // row = b*MAX_LEN + p

    float4 v[ROWS_PER_WARP][3];
    bool   zero[ROWS_PER_WARP];

    #pragma unroll
    for (int r = 0; r < ROWS_PER_WARP; ++r) {
        const int bp  = row0 + r;
        const int bb  = bp >> 12;             // / MAX_LEN
        const int idx = __ldg(&g_idx[bp]);    // uniform across warp -> broadcast
        zero[r] = (idx < 0);
        const int idc = zero[r] ? 0 : idx;    // clamp: load valid row anyway
        const float4* src = x + ((long long)bb * T + idc) * D4;
        v[r][0] = __ldg(src + lane);
        v[r][1] = __ldg(src + lane + 32);
        v[r][2] = __ldg(src + lane + 64);
    }

    const float4 z = make_float4(0.f, 0.f, 0.f, 0.f);
    #pragma unroll
    for (int r = 0; r < ROWS_PER_WARP; ++r) {
        float4* dst = out + (long long)(row0 + r) * D4;
        float4 a = zero[r] ? z : v[r][0];
        float4 b4 = zero[r] ? z : v[r][1];
        float4 c = zero[r] ? z : v[r][2];
        __stcs(dst + lane,      a);
        __stcs(dst + lane + 32, b4);
        __stcs(dst + lane + 64, c);
    }
}

extern "C" void kernel_launch(void* const* d_in, const int* in_sizes, int n_in,
                              void* d_out, int out_size)
{
    const float* x        = (const float*)d_in[0];
    const int*   duration = (const int*)d_in[1];

    float* out = (float*)d_out;
    float* out_tail = out + (size_t)B * MAX_LEN * D;   // mel_len region (64 floats)

    lr_scan_scatter<<<B, T>>>(duration, out_tail);

    const int total_warps = (B * MAX_LEN) / ROWS_PER_WARP;   // 65536
    const int threads = 256;
    const int blocks  = total_warps * 32 / threads;          // 8192
    lr_gather<<<blocks, threads>>>((const float4*)x, (float4*)out);
}